// round 12
// baseline (speedup 1.0000x reference)
#include <cuda_runtime.h>
#include <cuda_fp16.h>
#include <cstdint>

// ---------------------------------------------------------------------------
// Problem constants
// ---------------------------------------------------------------------------
#define NTOK 4096
#define CDIM 1024
#define NHEAD 16
#define HDIM 64
#define MDIM 4096
#define QKVDIM 3072

// q pre-scale: (1/sqrt(64)) * log2(e)  -> softmax uses raw ex2
#define QSCALE 0.1803368801111204f

// ---------------------------------------------------------------------------
// Scratch (device globals — no allocations allowed)
// ---------------------------------------------------------------------------
__device__ __half g_h  [(size_t)NTOK * CDIM];
__device__ __half g_qkv[(size_t)NTOK * QKVDIM];   // q pre-scaled by QSCALE
__device__ __half g_o  [(size_t)NTOK * CDIM];
__device__ float  g_x1 [(size_t)NTOK * CDIM];
__device__ __half g_h2 [(size_t)NTOK * CDIM];
__device__ __half g_t  [(size_t)NTOK * MDIM];
__device__ __half g_wqkv_h[(size_t)CDIM * QKVDIM];
__device__ __half g_wo_h  [(size_t)CDIM * CDIM];
__device__ __half g_w1_h  [(size_t)CDIM * MDIM];
__device__ __half g_w2_h  [(size_t)MDIM * CDIM];

// ---------------------------------------------------------------------------
// Helpers
// ---------------------------------------------------------------------------
__device__ __forceinline__ float gelu_tanh(float x) {
    const float u = 0.7978845608028654f * (x + 0.044715f * x * x * x);
    return 0.5f * x * (1.0f + tanhf(u));
}
__device__ __forceinline__ float ex2f(float x) {
    float r;
    asm("ex2.approx.f32 %0, %1;" : "=f"(r) : "f"(x));
    return r;
}
__device__ __forceinline__ uint32_t packh2(float a, float b) {
    __half2 v = __floats2half2_rn(a, b);
    return *reinterpret_cast<uint32_t*>(&v);
}
__device__ __forceinline__ void mma_f16(float* c, const uint32_t* a,
                                        const uint32_t* b) {
    asm volatile(
        "mma.sync.aligned.m16n8k16.row.col.f32.f16.f16.f32 "
        "{%0,%1,%2,%3}, {%4,%5,%6,%7}, {%8,%9}, {%0,%1,%2,%3};"
        : "+f"(c[0]), "+f"(c[1]), "+f"(c[2]), "+f"(c[3])
        : "r"(a[0]), "r"(a[1]), "r"(a[2]), "r"(a[3]),
          "r"(b[0]), "r"(b[1]));
}
__device__ __forceinline__ void ldsm4(uint32_t* d, uint32_t a) {
    asm volatile("ldmatrix.sync.aligned.m8n8.x4.shared.b16 "
                 "{%0,%1,%2,%3}, [%4];"
                 : "=r"(d[0]), "=r"(d[1]), "=r"(d[2]), "=r"(d[3]) : "r"(a));
}
__device__ __forceinline__ void ldsm4t(uint32_t* d, uint32_t a) {
    asm volatile("ldmatrix.sync.aligned.m8n8.x4.trans.shared.b16 "
                 "{%0,%1,%2,%3}, [%4];"
                 : "=r"(d[0]), "=r"(d[1]), "=r"(d[2]), "=r"(d[3]) : "r"(a));
}
__device__ __forceinline__ void cp16(void* smem, const void* gmem) {
    uint32_t s = (uint32_t)__cvta_generic_to_shared(smem);
    asm volatile("cp.async.cg.shared.global [%0], [%1], 16;"
                 :: "r"(s), "l"(gmem));
}

// ---------------------------------------------------------------------------
// Fused fp32->fp16 conversion, all four weights, one launch.
// Per-BLOCK segment select (1024 quads per block; every segment size is a
// multiple of 1024 quads so no block straddles), 4 independent loads/thread.
// ---------------------------------------------------------------------------
#define N4_QKV ((CDIM * QKVDIM) / 4)
#define N4_WO  ((CDIM * CDIM) / 4)
#define N4_W1  ((CDIM * MDIM) / 4)
#define N4_W2  ((MDIM * CDIM) / 4)
#define N4_TOTAL (N4_QKV + N4_WO + N4_W1 + N4_W2)

__global__ __launch_bounds__(256) void f2h_all_kernel(
    const float* __restrict__ wqkv, const float* __restrict__ wo,
    const float* __restrict__ w1,   const float* __restrict__ w2,
    __half* __restrict__ dqkv, __half* __restrict__ dwo,
    __half* __restrict__ dw1,  __half* __restrict__ dw2)
{
    const int qb = blockIdx.x * 1024;     // block's first quad index
    const float* src;
    __half* dst;
    int base;
    if (qb < N4_QKV)                      { src = wqkv; dst = dqkv; base = 0; }
    else if (qb < N4_QKV + N4_WO)         { src = wo;  dst = dwo;
                                            base = N4_QKV; }
    else if (qb < N4_QKV + N4_WO + N4_W1) { src = w1;  dst = dw1;
                                            base = N4_QKV + N4_WO; }
    else                                  { src = w2;  dst = dw2;
                                            base = N4_QKV + N4_WO + N4_W1; }
    const int i0 = qb - base + threadIdx.x;
    float4 v[4];
    #pragma unroll
    for (int r = 0; r < 4; r++)
        v[r] = ((const float4*)src)[i0 + r * 256];
    #pragma unroll
    for (int r = 0; r < 4; r++) {
        uint2 o;
        o.x = packh2(v[r].x, v[r].y);
        o.y = packh2(v[r].z, v[r].w);
        ((uint2*)dst)[i0 + r * 256] = o;
    }
}

// ---------------------------------------------------------------------------
// RMSNorm: one block per row, fp16 output
// ---------------------------------------------------------------------------
__global__ __launch_bounds__(256) void rmsnorm_kernel(
    const float* __restrict__ x, const float* __restrict__ g,
    __half* __restrict__ out)
{
    const int row = blockIdx.x;
    const int tid = threadIdx.x;
    const float4 v = ((const float4*)(x + (size_t)row * CDIM))[tid];
    float ss = v.x * v.x + v.y * v.y + v.z * v.z + v.w * v.w;
    #pragma unroll
    for (int o = 16; o; o >>= 1) ss += __shfl_xor_sync(0xffffffffu, ss, o);
    __shared__ float wsum[8];
    if ((tid & 31) == 0) wsum[tid >> 5] = ss;
    __syncthreads();
    float tot = wsum[0] + wsum[1] + wsum[2] + wsum[3]
              + wsum[4] + wsum[5] + wsum[6] + wsum[7];
    const float inv = rsqrtf(tot * (1.0f / (float)CDIM) + 1e-6f);
    const float4 gv = ((const float4*)g)[tid];
    uint2 o;
    o.x = packh2(v.x * inv * gv.x, v.y * inv * gv.y);
    o.y = packh2(v.z * inv * gv.z, v.w * inv * gv.w);
    ((uint2*)(out + (size_t)row * CDIM))[tid] = o;
}

// ---------------------------------------------------------------------------
// FP16 GEMM: 128x128x32 tile, 8 warps (warp 64x32), mma.m16n8k16, ldmatrix,
// 4-stage cp.async pipeline (wait_group 2 steady state).
// MODE 1: float C = acc + R
// MODE 2: half  C = gelu(acc)
// MODE 3: half  C = acc * (col<CDIM ? QSCALE : 1)
// ---------------------------------------------------------------------------
#define AHS 40    // A smem row stride (halves): 32 + 8 pad
#define BHS 136   // B smem row stride (halves): 128 + 8 pad
#define A_STAGE (128 * AHS)
#define B_STAGE (32 * BHS)
#define NSTAGE 4
#define G_SMEM (NSTAGE * (A_STAGE + B_STAGE) * 2)

template <int MODE>
__global__ __launch_bounds__(256) void hgemm_kernel(
    const __half* __restrict__ A, const __half* __restrict__ B,
    const float* __restrict__ R, void* __restrict__ Cv,
    int M, int N, int K)
{
    extern __shared__ __half dsm[];
    __half* Asm = dsm;
    __half* Bsm = dsm + NSTAGE * A_STAGE;

    const int tid  = threadIdx.x;
    const int bm   = blockIdx.y * 128;
    const int bn   = blockIdx.x * 128;
    const int warp = tid >> 5;
    const int lane = tid & 31;
    const int wm   = (warp >> 2) << 6;   // 0 / 64
    const int wn   = (warp & 3) << 5;    // 0,32,64,96
    const int lr   = lane >> 2;
    const int lc   = lane & 3;

    float acc[4][4][4];
    #pragma unroll
    for (int mt = 0; mt < 4; mt++)
        #pragma unroll
        for (int nt = 0; nt < 4; nt++)
            #pragma unroll
            for (int i = 0; i < 4; i++) acc[mt][nt][i] = 0.0f;

    auto prefetch = [&](int st, int k0) {
        __half* Ad = Asm + st * A_STAGE;
        __half* Bd = Bsm + st * B_STAGE;
        #pragma unroll
        for (int r = 0; r < 2; r++) {
            const int c  = tid + (r << 8);          // 0..511
            const int am = c >> 2;                   // 0..127
            const int ak = (c & 3) << 3;             // 0,8,16,24
            cp16(&Ad[am * AHS + ak],
                 A + (size_t)(bm + am) * K + k0 + ak);
            const int bk = c >> 4;                   // 0..31
            const int bq = (c & 15) << 3;            // 0..120
            cp16(&Bd[bk * BHS + bq],
                 B + (size_t)(k0 + bk) * N + bn + bq);
        }
        asm volatile("cp.async.commit_group;");
    };

    const int nch = K / 32;
    prefetch(0, 0);
    prefetch(1, 32);
    prefetch(2, 64);

    const int a_row = lane & 15;
    const int a_hi  = (lane >> 4) << 3;
    const int b_row = (lane & 7) + ((lane >> 3) & 1) * 8;
    const int b_col = (lane >> 4) << 3;

    int buf = 0;
    for (int i = 0; i < nch; i++) {
        const int rem = nch - 1 - i;
        if (rem >= 2)      asm volatile("cp.async.wait_group 2;");
        else if (rem == 1) asm volatile("cp.async.wait_group 1;");
        else               asm volatile("cp.async.wait_group 0;");
        __syncthreads();
        if (i + 3 < nch) {
            int nst = buf + 3; if (nst >= NSTAGE) nst -= NSTAGE;
            prefetch(nst, (i + 3) * 32);
        }

        const uint32_t abase =
            (uint32_t)__cvta_generic_to_shared(Asm + buf * A_STAGE);
        const uint32_t bbase =
            (uint32_t)__cvta_generic_to_shared(Bsm + buf * B_STAGE);

        #pragma unroll
        for (int ks = 0; ks < 2; ks++) {
            uint32_t af[4][4], bf[2][4];
            #pragma unroll
            for (int mt = 0; mt < 4; mt++)
                ldsm4(af[mt], abase + 2 * ((wm + mt * 16 + a_row) * AHS
                                           + ks * 16 + a_hi));
            #pragma unroll
            for (int p = 0; p < 2; p++)
                ldsm4t(bf[p], bbase + 2 * ((ks * 16 + b_row) * BHS
                                           + wn + p * 16 + b_col));
            #pragma unroll
            for (int mt = 0; mt < 4; mt++)
                #pragma unroll
                for (int nt = 0; nt < 4; nt++)
                    mma_f16(acc[mt][nt], af[mt], &bf[nt >> 1][(nt & 1) * 2]);
        }
        buf++; if (buf >= NSTAGE) buf -= NSTAGE;
    }

    #pragma unroll
    for (int mt = 0; mt < 4; mt++) {
        const int row0 = bm + wm + mt * 16 + lr;
        #pragma unroll
        for (int nt = 0; nt < 4; nt++) {
            const int col = bn + wn + nt * 8 + lc * 2;
            #pragma unroll
            for (int half_ = 0; half_ < 2; half_++) {
                const size_t row = (size_t)(row0 + half_ * 8);
                float vx = acc[mt][nt][half_ * 2];
                float vy = acc[mt][nt][half_ * 2 + 1];
                if (MODE == 1) {
                    const float2 r2 = *(const float2*)(R + row * N + col);
                    float* C = (float*)Cv;
                    *(float2*)(C + row * N + col) =
                        make_float2(vx + r2.x, vy + r2.y);
                } else if (MODE == 2) {
                    __half* C = (__half*)Cv;
                    *(__half2*)(C + row * N + col) =
                        __floats2half2_rn(gelu_tanh(vx), gelu_tanh(vy));
                } else {
                    const float s = (col < CDIM) ? QSCALE : 1.0f;
                    __half* C = (__half*)Cv;
                    *(__half2*)(C + row * N + col) =
                        __floats2half2_rn(vx * s, vy * s);
                }
            }
        }
    }
}

// ---------------------------------------------------------------------------
// FP16 flash attention: 128 threads (4 warps), 64 queries/CTA, 64-key tiles,
// double-buffered K/V, register-repacked P. Scores arrive in the log2 domain
// (q pre-scaled by QSCALE) so softmax uses bare ex2.approx.
// ---------------------------------------------------------------------------
#define FHS 72   // smem row stride (halves): 64 + 8 pad

__global__ __launch_bounds__(128) void flash_h_kernel(
    const __half* __restrict__ qkv, __half* __restrict__ o)
{
    __shared__ __half Qs[64 * FHS];
    __shared__ __half Ks[2][64 * FHS];
    __shared__ __half Vs[2][64 * FHS];

    const int tid  = threadIdx.x;
    const int warp = tid >> 5;
    const int lane = tid & 31;
    const int lr   = lane >> 2;
    const int lc   = lane & 3;
    const int hd   = blockIdx.y;
    const int q0   = blockIdx.x * 64;

    #pragma unroll
    for (int s = 0; s < 4; s++) {
        const int c  = tid + s * 128;
        const int r  = c >> 3;
        const int cq = (c & 7) << 3;
        *(uint4*)(Qs + r * FHS + cq) =
            *(const uint4*)(qkv + (size_t)(q0 + r) * QKVDIM
                            + hd * HDIM + cq);
    }

    auto prefetch = [&](int buf, int k0) {
        const __half* Kp = qkv + (size_t)k0 * QKVDIM + CDIM + hd * HDIM;
        const __half* Vp = Kp + CDIM;
        #pragma unroll
        for (int s = 0; s < 4; s++) {
            const int c  = tid + s * 128;
            const int r  = c >> 3;
            const int cq = (c & 7) << 3;
            cp16(&Ks[buf][r * FHS + cq], Kp + (size_t)r * QKVDIM + cq);
            cp16(&Vs[buf][r * FHS + cq], Vp + (size_t)r * QKVDIM + cq);
        }
        asm volatile("cp.async.commit_group;");
    };

    prefetch(0, 0);
    __syncthreads();

    uint32_t qf[4][4];
    {
        const uint32_t qbase = (uint32_t)__cvta_generic_to_shared(Qs);
        const int a_row = warp * 16 + (lane & 15);
        const int a_hi  = (lane >> 4) << 3;
        #pragma unroll
        for (int j = 0; j < 4; j++)
            ldsm4(qf[j], qbase + 2 * (a_row * FHS + j * 16 + a_hi));
    }

    float m0 = -1e30f, m1 = -1e30f, l0 = 0.0f, l1 = 0.0f;
    float oacc[8][4];
    #pragma unroll
    for (int nt = 0; nt < 8; nt++)
        #pragma unroll
        for (int i = 0; i < 4; i++) oacc[nt][i] = 0.0f;

    const int b_row = (lane & 7) + ((lane >> 3) & 1) * 8;
    const int b_col = (lane >> 4) << 3;
    const int k_row = lane & 7;
    const int k_r2  = ((lane >> 4) & 1) * 8;
    const int k_col = ((lane >> 3) & 1) * 8;

    int buf = 0;
    for (int kt = 0; kt < NTOK / 64; kt++) {
        asm volatile("cp.async.wait_group 0;");
        __syncthreads();
        if (kt + 1 < NTOK / 64) prefetch(buf ^ 1, (kt + 1) * 64);

        const uint32_t kbase =
            (uint32_t)__cvta_generic_to_shared(&Ks[buf][0]);
        const uint32_t vbase =
            (uint32_t)__cvta_generic_to_shared(&Vs[buf][0]);

        float sacc[8][4];
        #pragma unroll
        for (int nt = 0; nt < 8; nt++)
            #pragma unroll
            for (int i = 0; i < 4; i++) sacc[nt][i] = 0.0f;

        #pragma unroll
        for (int j = 0; j < 4; j++) {
            uint32_t kf[4][4];
            #pragma unroll
            for (int p = 0; p < 4; p++)
                ldsm4(kf[p], kbase + 2 * ((p * 16 + k_row + k_r2) * FHS
                                          + j * 16 + k_col));
            #pragma unroll
            for (int nt = 0; nt < 8; nt++)
                mma_f16(sacc[nt], qf[j], &kf[nt >> 1][(nt & 1) * 2]);
        }

        float mx0 = -1e30f, mx1 = -1e30f;
        #pragma unroll
        for (int nt = 0; nt < 8; nt++) {
            mx0 = fmaxf(mx0, fmaxf(sacc[nt][0], sacc[nt][1]));
            mx1 = fmaxf(mx1, fmaxf(sacc[nt][2], sacc[nt][3]));
        }
        mx0 = fmaxf(mx0, __shfl_xor_sync(0xffffffffu, mx0, 1));
        mx0 = fmaxf(mx0, __shfl_xor_sync(0xffffffffu, mx0, 2));
        mx1 = fmaxf(mx1, __shfl_xor_sync(0xffffffffu, mx1, 1));
        mx1 = fmaxf(mx1, __shfl_xor_sync(0xffffffffu, mx1, 2));

        const float mn0 = fmaxf(m0, mx0);
        const float mn1 = fmaxf(m1, mx1);
        const float c0 = ex2f(m0 - mn0);
        const float c1 = ex2f(m1 - mn1);
        m0 = mn0; m1 = mn1;

        float rs0 = 0.0f, rs1 = 0.0f;
        #pragma unroll
        for (int nt = 0; nt < 8; nt++) {
            sacc[nt][0] = ex2f(sacc[nt][0] - mn0);
            sacc[nt][1] = ex2f(sacc[nt][1] - mn0);
            sacc[nt][2] = ex2f(sacc[nt][2] - mn1);
            sacc[nt][3] = ex2f(sacc[nt][3] - mn1);
            rs0 += sacc[nt][0] + sacc[nt][1];
            rs1 += sacc[nt][2] + sacc[nt][3];
        }
        rs0 += __shfl_xor_sync(0xffffffffu, rs0, 1);
        rs0 += __shfl_xor_sync(0xffffffffu, rs0, 2);
        rs1 += __shfl_xor_sync(0xffffffffu, rs1, 1);
        rs1 += __shfl_xor_sync(0xffffffffu, rs1, 2);
        l0 = l0 * c0 + rs0;
        l1 = l1 * c1 + rs1;

        #pragma unroll
        for (int nt = 0; nt < 8; nt++) {
            oacc[nt][0] *= c0; oacc[nt][1] *= c0;
            oacc[nt][2] *= c1; oacc[nt][3] *= c1;
        }

        #pragma unroll
        for (int j = 0; j < 4; j++) {
            uint32_t pf[4];
            pf[0] = packh2(sacc[2 * j][0],     sacc[2 * j][1]);
            pf[1] = packh2(sacc[2 * j][2],     sacc[2 * j][3]);
            pf[2] = packh2(sacc[2 * j + 1][0], sacc[2 * j + 1][1]);
            pf[3] = packh2(sacc[2 * j + 1][2], sacc[2 * j + 1][3]);
            uint32_t vf[4][4];
            #pragma unroll
            for (int p = 0; p < 4; p++)
                ldsm4t(vf[p], vbase + 2 * ((j * 16 + b_row) * FHS
                                           + p * 16 + b_col));
            #pragma unroll
            for (int nt = 0; nt < 8; nt++)
                mma_f16(oacc[nt], pf, &vf[nt >> 1][(nt & 1) * 2]);
        }
        __syncthreads();
        buf ^= 1;
    }

    const float inv0 = 1.0f / l0;
    const float inv1 = 1.0f / l1;
    const int r0 = q0 + warp * 16 + lr;
    #pragma unroll
    for (int nt = 0; nt < 8; nt++) {
        const int d = nt * 8 + lc * 2;
        *(__half2*)(o + (size_t)r0 * CDIM + hd * HDIM + d) =
            __floats2half2_rn(oacc[nt][0] * inv0, oacc[nt][1] * inv0);
        *(__half2*)(o + (size_t)(r0 + 8) * CDIM + hd * HDIM + d) =
            __floats2half2_rn(oacc[nt][2] * inv1, oacc[nt][3] * inv1);
    }
}

// ---------------------------------------------------------------------------
// Launcher
// ---------------------------------------------------------------------------
extern "C" void kernel_launch(void* const* d_in, const int* in_sizes, int n_in,
                              void* d_out, int out_size)
{
    const float* x     = (const float*)d_in[0];
    const float* g1    = (const float*)d_in[1];
    const float* g2    = (const float*)d_in[2];
    const float* w_qkv = (const float*)d_in[3];
    const float* w_o   = (const float*)d_in[4];
    const float* w1    = (const float*)d_in[5];
    const float* w2    = (const float*)d_in[6];
    float* out = (float*)d_out;

    __half *h, *qkv, *o, *h2, *t;
    __half *wqkv_h, *wo_h, *w1_h, *w2_h;
    float *x1;
    cudaGetSymbolAddress((void**)&h,   g_h);
    cudaGetSymbolAddress((void**)&qkv, g_qkv);
    cudaGetSymbolAddress((void**)&o,   g_o);
    cudaGetSymbolAddress((void**)&x1,  g_x1);
    cudaGetSymbolAddress((void**)&h2,  g_h2);
    cudaGetSymbolAddress((void**)&t,   g_t);
    cudaGetSymbolAddress((void**)&wqkv_h, g_wqkv_h);
    cudaGetSymbolAddress((void**)&wo_h,   g_wo_h);
    cudaGetSymbolAddress((void**)&w1_h,   g_w1_h);
    cudaGetSymbolAddress((void**)&w2_h,   g_w2_h);

    cudaFuncSetAttribute(hgemm_kernel<1>,
        cudaFuncAttributeMaxDynamicSharedMemorySize, G_SMEM);
    cudaFuncSetAttribute(hgemm_kernel<2>,
        cudaFuncAttributeMaxDynamicSharedMemorySize, G_SMEM);
    cudaFuncSetAttribute(hgemm_kernel<3>,
        cudaFuncAttributeMaxDynamicSharedMemorySize, G_SMEM);

    // 0) all weights -> fp16 in one launch (4 quads per thread)
    f2h_all_kernel<<<N4_TOTAL / 1024, 256>>>(
        w_qkv, w_o, w1, w2, wqkv_h, wo_h, w1_h, w2_h);

    // 1) h = rmsnorm(x, g1)
    rmsnorm_kernel<<<NTOK, 256>>>(x, g1, h);

    // 2) qkv = h @ w_qkv (q scaled by QSCALE = 0.125*log2e)
    hgemm_kernel<3><<<dim3(QKVDIM / 128, NTOK / 128), 256, G_SMEM>>>(
        h, wqkv_h, nullptr, qkv, NTOK, QKVDIM, CDIM);

    // 3) o = attention(qkv)
    flash_h_kernel<<<dim3(NTOK / 64, NHEAD), 128>>>(qkv, o);

    // 4) x1 = x + o @ w_o
    hgemm_kernel<1><<<dim3(CDIM / 128, NTOK / 128), 256, G_SMEM>>>(
        o, wo_h, x, x1, NTOK, CDIM, CDIM);

    // 5) h2 = rmsnorm(x1, g2)
    rmsnorm_kernel<<<NTOK, 256>>>(x1, g2, h2);

    // 6) t = gelu(h2 @ w1)
    hgemm_kernel<2><<<dim3(MDIM / 128, NTOK / 128), 256, G_SMEM>>>(
        h2, w1_h, nullptr, t, NTOK, MDIM, CDIM);

    // 7) out = x1 + t @ w2
    hgemm_kernel<1><<<dim3(CDIM / 128, NTOK / 128), 256, G_SMEM>>>(
        t, w2_h, x1, out, NTOK, CDIM, MDIM);
}

// round 13
// speedup vs baseline: 1.0382x; 1.0382x over previous
#include <cuda_runtime.h>
#include <cuda_fp16.h>
#include <cstdint>

// ---------------------------------------------------------------------------
// Problem constants
// ---------------------------------------------------------------------------
#define NTOK 4096
#define CDIM 1024
#define NHEAD 16
#define HDIM 64
#define MDIM 4096
#define QKVDIM 3072

// q pre-scale: (1/sqrt(64)) * log2(e)  -> softmax uses raw ex2
#define QSCALE 0.1803368801111204f

// ---------------------------------------------------------------------------
// Scratch (device globals — no allocations allowed)
// ---------------------------------------------------------------------------
__device__ __half g_h  [(size_t)NTOK * CDIM];
__device__ __half g_qkv[(size_t)NTOK * QKVDIM];   // q pre-scaled by QSCALE
__device__ __half g_o  [(size_t)NTOK * CDIM];
__device__ float  g_x1 [(size_t)NTOK * CDIM];
__device__ __half g_h2 [(size_t)NTOK * CDIM];
__device__ __half g_t  [(size_t)NTOK * MDIM];
__device__ __half g_wqkv_h[(size_t)CDIM * QKVDIM];
__device__ __half g_wo_h  [(size_t)CDIM * CDIM];
__device__ __half g_w1_h  [(size_t)CDIM * MDIM];
__device__ __half g_w2_h  [(size_t)MDIM * CDIM];

// ---------------------------------------------------------------------------
// Helpers
// ---------------------------------------------------------------------------
__device__ __forceinline__ float gelu_tanh(float x) {
    const float u = 0.7978845608028654f * (x + 0.044715f * x * x * x);
    return 0.5f * x * (1.0f + tanhf(u));
}
__device__ __forceinline__ float ex2f(float x) {
    float r;
    asm("ex2.approx.f32 %0, %1;" : "=f"(r) : "f"(x));
    return r;
}
__device__ __forceinline__ uint32_t packh2(float a, float b) {
    __half2 v = __floats2half2_rn(a, b);
    return *reinterpret_cast<uint32_t*>(&v);
}
__device__ __forceinline__ void mma_f16(float* c, const uint32_t* a,
                                        const uint32_t* b) {
    asm volatile(
        "mma.sync.aligned.m16n8k16.row.col.f32.f16.f16.f32 "
        "{%0,%1,%2,%3}, {%4,%5,%6,%7}, {%8,%9}, {%0,%1,%2,%3};"
        : "+f"(c[0]), "+f"(c[1]), "+f"(c[2]), "+f"(c[3])
        : "r"(a[0]), "r"(a[1]), "r"(a[2]), "r"(a[3]),
          "r"(b[0]), "r"(b[1]));
}
__device__ __forceinline__ void ldsm4(uint32_t* d, uint32_t a) {
    asm volatile("ldmatrix.sync.aligned.m8n8.x4.shared.b16 "
                 "{%0,%1,%2,%3}, [%4];"
                 : "=r"(d[0]), "=r"(d[1]), "=r"(d[2]), "=r"(d[3]) : "r"(a));
}
__device__ __forceinline__ void ldsm4t(uint32_t* d, uint32_t a) {
    asm volatile("ldmatrix.sync.aligned.m8n8.x4.trans.shared.b16 "
                 "{%0,%1,%2,%3}, [%4];"
                 : "=r"(d[0]), "=r"(d[1]), "=r"(d[2]), "=r"(d[3]) : "r"(a));
}
__device__ __forceinline__ void cp16(void* smem, const void* gmem) {
    uint32_t s = (uint32_t)__cvta_generic_to_shared(smem);
    asm volatile("cp.async.cg.shared.global [%0], [%1], 16;"
                 :: "r"(s), "l"(gmem));
}

// ---------------------------------------------------------------------------
// Fused fp32->fp16 conversion of ALL four weight matrices in one launch
// (R11-proven version).
// ---------------------------------------------------------------------------
#define N4_QKV ((CDIM * QKVDIM) / 4)
#define N4_WO  ((CDIM * CDIM) / 4)
#define N4_W1  ((CDIM * MDIM) / 4)
#define N4_W2  ((MDIM * CDIM) / 4)
#define N4_TOTAL (N4_QKV + N4_WO + N4_W1 + N4_W2)

__global__ __launch_bounds__(256) void f2h_all_kernel(
    const float* __restrict__ wqkv, const float* __restrict__ wo,
    const float* __restrict__ w1,   const float* __restrict__ w2,
    __half* __restrict__ dqkv, __half* __restrict__ dwo,
    __half* __restrict__ dw1,  __half* __restrict__ dw2)
{
    int i = blockIdx.x * 256 + threadIdx.x;
    if (i >= N4_TOTAL) return;
    const float* src;
    __half* dst;
    if (i < N4_QKV)                       { src = wqkv; dst = dqkv; }
    else if (i < N4_QKV + N4_WO)          { src = wo;  dst = dwo;  i -= N4_QKV; }
    else if (i < N4_QKV + N4_WO + N4_W1)  { src = w1;  dst = dw1;  i -= N4_QKV + N4_WO; }
    else                                  { src = w2;  dst = dw2;  i -= N4_QKV + N4_WO + N4_W1; }
    const float4 v = ((const float4*)src)[i];
    uint2 o;
    o.x = packh2(v.x, v.y);
    o.y = packh2(v.z, v.w);
    ((uint2*)dst)[i] = o;
}

// ---------------------------------------------------------------------------
// RMSNorm: one block per row, fp16 output
// ---------------------------------------------------------------------------
__global__ __launch_bounds__(256) void rmsnorm_kernel(
    const float* __restrict__ x, const float* __restrict__ g,
    __half* __restrict__ out)
{
    const int row = blockIdx.x;
    const int tid = threadIdx.x;
    const float4 v = ((const float4*)(x + (size_t)row * CDIM))[tid];
    float ss = v.x * v.x + v.y * v.y + v.z * v.z + v.w * v.w;
    #pragma unroll
    for (int o = 16; o; o >>= 1) ss += __shfl_xor_sync(0xffffffffu, ss, o);
    __shared__ float wsum[8];
    if ((tid & 31) == 0) wsum[tid >> 5] = ss;
    __syncthreads();
    float tot = wsum[0] + wsum[1] + wsum[2] + wsum[3]
              + wsum[4] + wsum[5] + wsum[6] + wsum[7];
    const float inv = rsqrtf(tot * (1.0f / (float)CDIM) + 1e-6f);
    const float4 gv = ((const float4*)g)[tid];
    uint2 o;
    o.x = packh2(v.x * inv * gv.x, v.y * inv * gv.y);
    o.y = packh2(v.z * inv * gv.z, v.w * inv * gv.w);
    ((uint2*)(out + (size_t)row * CDIM))[tid] = o;
}

// ---------------------------------------------------------------------------
// FP16 GEMM (R8/R11-proven): 128x128x32 tile, 8 warps (warp 64x32),
// mma.m16n8k16, ldmatrix, 3-stage cp.async pipeline, 256 threads.
// MODE 1: float C = acc + R
// MODE 2: half  C = gelu(acc)
// MODE 3: half  C = acc * (col<CDIM ? QSCALE : 1)
// ---------------------------------------------------------------------------
#define AHS 40    // A smem row stride (halves): 32 + 8 pad
#define BHS 136   // B smem row stride (halves): 128 + 8 pad
#define A_STAGE (128 * AHS)
#define B_STAGE (32 * BHS)
#define G_SMEM (3 * (A_STAGE + B_STAGE) * 2)

template <int MODE>
__global__ __launch_bounds__(256) void hgemm_kernel(
    const __half* __restrict__ A, const __half* __restrict__ B,
    const float* __restrict__ R, void* __restrict__ Cv,
    int M, int N, int K)
{
    extern __shared__ __half dsm[];
    __half* Asm = dsm;                 // 3 stages of 128x32 (+pad)
    __half* Bsm = dsm + 3 * A_STAGE;   // 3 stages of 32x128 (+pad)

    const int tid  = threadIdx.x;
    const int bm   = blockIdx.y * 128;
    const int bn   = blockIdx.x * 128;
    const int warp = tid >> 5;
    const int lane = tid & 31;
    const int wm   = (warp >> 2) << 6;   // 0 / 64
    const int wn   = (warp & 3) << 5;    // 0,32,64,96
    const int lr   = lane >> 2;
    const int lc   = lane & 3;

    float acc[4][4][4];
    #pragma unroll
    for (int mt = 0; mt < 4; mt++)
        #pragma unroll
        for (int nt = 0; nt < 4; nt++)
            #pragma unroll
            for (int i = 0; i < 4; i++) acc[mt][nt][i] = 0.0f;

    auto prefetch = [&](int st, int k0) {
        __half* Ad = Asm + st * A_STAGE;
        __half* Bd = Bsm + st * B_STAGE;
        #pragma unroll
        for (int r = 0; r < 2; r++) {
            const int c  = tid + (r << 8);          // 0..511
            const int am = c >> 2;                   // 0..127
            const int ak = (c & 3) << 3;             // 0,8,16,24
            cp16(&Ad[am * AHS + ak],
                 A + (size_t)(bm + am) * K + k0 + ak);
            const int bk = c >> 4;                   // 0..31
            const int bq = (c & 15) << 3;            // 0..120
            cp16(&Bd[bk * BHS + bq],
                 B + (size_t)(k0 + bk) * N + bn + bq);
        }
        asm volatile("cp.async.commit_group;");
    };

    prefetch(0, 0);
    prefetch(1, 32);

    const int a_row = lane & 15;
    const int a_hi  = (lane >> 4) << 3;
    const int b_row = (lane & 7) + ((lane >> 3) & 1) * 8;
    const int b_col = (lane >> 4) << 3;

    int buf = 0;
    for (int k0 = 0; k0 < K; k0 += 32) {
        if (k0 + 32 < K)
            asm volatile("cp.async.wait_group 1;");
        else
            asm volatile("cp.async.wait_group 0;");
        __syncthreads();
        if (k0 + 64 < K) {
            int nst = buf + 2; if (nst >= 3) nst -= 3;
            prefetch(nst, k0 + 64);
        }

        const uint32_t abase =
            (uint32_t)__cvta_generic_to_shared(Asm + buf * A_STAGE);
        const uint32_t bbase =
            (uint32_t)__cvta_generic_to_shared(Bsm + buf * B_STAGE);

        #pragma unroll
        for (int ks = 0; ks < 2; ks++) {
            uint32_t af[4][4], bf[2][4];
            #pragma unroll
            for (int mt = 0; mt < 4; mt++)
                ldsm4(af[mt], abase + 2 * ((wm + mt * 16 + a_row) * AHS
                                           + ks * 16 + a_hi));
            #pragma unroll
            for (int p = 0; p < 2; p++)
                ldsm4t(bf[p], bbase + 2 * ((ks * 16 + b_row) * BHS
                                           + wn + p * 16 + b_col));
            #pragma unroll
            for (int mt = 0; mt < 4; mt++)
                #pragma unroll
                for (int nt = 0; nt < 4; nt++)
                    mma_f16(acc[mt][nt], af[mt], &bf[nt >> 1][(nt & 1) * 2]);
        }
        buf++; if (buf >= 3) buf -= 3;
    }

    #pragma unroll
    for (int mt = 0; mt < 4; mt++) {
        const int row0 = bm + wm + mt * 16 + lr;
        #pragma unroll
        for (int nt = 0; nt < 4; nt++) {
            const int col = bn + wn + nt * 8 + lc * 2;
            #pragma unroll
            for (int half_ = 0; half_ < 2; half_++) {
                const size_t row = (size_t)(row0 + half_ * 8);
                float vx = acc[mt][nt][half_ * 2];
                float vy = acc[mt][nt][half_ * 2 + 1];
                if (MODE == 1) {
                    const float2 r2 = *(const float2*)(R + row * N + col);
                    float* C = (float*)Cv;
                    *(float2*)(C + row * N + col) =
                        make_float2(vx + r2.x, vy + r2.y);
                } else if (MODE == 2) {
                    __half* C = (__half*)Cv;
                    *(__half2*)(C + row * N + col) =
                        __floats2half2_rn(gelu_tanh(vx), gelu_tanh(vy));
                } else {
                    const float s = (col < CDIM) ? QSCALE : 1.0f;
                    __half* C = (__half*)Cv;
                    *(__half2*)(C + row * N + col) =
                        __floats2half2_rn(vx * s, vy * s);
                }
            }
        }
    }
}

// ---------------------------------------------------------------------------
// FP16 flash attention: 128 threads (4 warps), 64 queries/CTA, 64-key tiles,
// double-buffered K/V, register-repacked P. Scores arrive in the log2 domain
// (q pre-scaled by QSCALE) so softmax uses bare ex2.approx.
// ---------------------------------------------------------------------------
#define FHS 72   // smem row stride (halves): 64 + 8 pad

__global__ __launch_bounds__(128) void flash_h_kernel(
    const __half* __restrict__ qkv, __half* __restrict__ o)
{
    __shared__ __half Qs[64 * FHS];
    __shared__ __half Ks[2][64 * FHS];
    __shared__ __half Vs[2][64 * FHS];

    const int tid  = threadIdx.x;
    const int warp = tid >> 5;
    const int lane = tid & 31;
    const int lr   = lane >> 2;
    const int lc   = lane & 3;
    const int hd   = blockIdx.y;
    const int q0   = blockIdx.x * 64;

    #pragma unroll
    for (int s = 0; s < 4; s++) {
        const int c  = tid + s * 128;
        const int r  = c >> 3;
        const int cq = (c & 7) << 3;
        *(uint4*)(Qs + r * FHS + cq) =
            *(const uint4*)(qkv + (size_t)(q0 + r) * QKVDIM
                            + hd * HDIM + cq);
    }

    auto prefetch = [&](int buf, int k0) {
        const __half* Kp = qkv + (size_t)k0 * QKVDIM + CDIM + hd * HDIM;
        const __half* Vp = Kp + CDIM;
        #pragma unroll
        for (int s = 0; s < 4; s++) {
            const int c  = tid + s * 128;
            const int r  = c >> 3;
            const int cq = (c & 7) << 3;
            cp16(&Ks[buf][r * FHS + cq], Kp + (size_t)r * QKVDIM + cq);
            cp16(&Vs[buf][r * FHS + cq], Vp + (size_t)r * QKVDIM + cq);
        }
        asm volatile("cp.async.commit_group;");
    };

    prefetch(0, 0);
    __syncthreads();

    uint32_t qf[4][4];
    {
        const uint32_t qbase = (uint32_t)__cvta_generic_to_shared(Qs);
        const int a_row = warp * 16 + (lane & 15);
        const int a_hi  = (lane >> 4) << 3;
        #pragma unroll
        for (int j = 0; j < 4; j++)
            ldsm4(qf[j], qbase + 2 * (a_row * FHS + j * 16 + a_hi));
    }

    float m0 = -1e30f, m1 = -1e30f, l0 = 0.0f, l1 = 0.0f;
    float oacc[8][4];
    #pragma unroll
    for (int nt = 0; nt < 8; nt++)
        #pragma unroll
        for (int i = 0; i < 4; i++) oacc[nt][i] = 0.0f;

    const int b_row = (lane & 7) + ((lane >> 3) & 1) * 8;
    const int b_col = (lane >> 4) << 3;
    const int k_row = lane & 7;
    const int k_r2  = ((lane >> 4) & 1) * 8;
    const int k_col = ((lane >> 3) & 1) * 8;

    int buf = 0;
    for (int kt = 0; kt < NTOK / 64; kt++) {
        asm volatile("cp.async.wait_group 0;");
        __syncthreads();
        if (kt + 1 < NTOK / 64) prefetch(buf ^ 1, (kt + 1) * 64);

        const uint32_t kbase =
            (uint32_t)__cvta_generic_to_shared(&Ks[buf][0]);
        const uint32_t vbase =
            (uint32_t)__cvta_generic_to_shared(&Vs[buf][0]);

        float sacc[8][4];
        #pragma unroll
        for (int nt = 0; nt < 8; nt++)
            #pragma unroll
            for (int i = 0; i < 4; i++) sacc[nt][i] = 0.0f;

        #pragma unroll
        for (int j = 0; j < 4; j++) {
            uint32_t kf[4][4];
            #pragma unroll
            for (int p = 0; p < 4; p++)
                ldsm4(kf[p], kbase + 2 * ((p * 16 + k_row + k_r2) * FHS
                                          + j * 16 + k_col));
            #pragma unroll
            for (int nt = 0; nt < 8; nt++)
                mma_f16(sacc[nt], qf[j], &kf[nt >> 1][(nt & 1) * 2]);
        }

        float mx0 = -1e30f, mx1 = -1e30f;
        #pragma unroll
        for (int nt = 0; nt < 8; nt++) {
            mx0 = fmaxf(mx0, fmaxf(sacc[nt][0], sacc[nt][1]));
            mx1 = fmaxf(mx1, fmaxf(sacc[nt][2], sacc[nt][3]));
        }
        mx0 = fmaxf(mx0, __shfl_xor_sync(0xffffffffu, mx0, 1));
        mx0 = fmaxf(mx0, __shfl_xor_sync(0xffffffffu, mx0, 2));
        mx1 = fmaxf(mx1, __shfl_xor_sync(0xffffffffu, mx1, 1));
        mx1 = fmaxf(mx1, __shfl_xor_sync(0xffffffffu, mx1, 2));

        const float mn0 = fmaxf(m0, mx0);
        const float mn1 = fmaxf(m1, mx1);
        const float c0 = ex2f(m0 - mn0);
        const float c1 = ex2f(m1 - mn1);
        m0 = mn0; m1 = mn1;

        float rs0 = 0.0f, rs1 = 0.0f;
        #pragma unroll
        for (int nt = 0; nt < 8; nt++) {
            sacc[nt][0] = ex2f(sacc[nt][0] - mn0);
            sacc[nt][1] = ex2f(sacc[nt][1] - mn0);
            sacc[nt][2] = ex2f(sacc[nt][2] - mn1);
            sacc[nt][3] = ex2f(sacc[nt][3] - mn1);
            rs0 += sacc[nt][0] + sacc[nt][1];
            rs1 += sacc[nt][2] + sacc[nt][3];
        }
        rs0 += __shfl_xor_sync(0xffffffffu, rs0, 1);
        rs0 += __shfl_xor_sync(0xffffffffu, rs0, 2);
        rs1 += __shfl_xor_sync(0xffffffffu, rs1, 1);
        rs1 += __shfl_xor_sync(0xffffffffu, rs1, 2);
        l0 = l0 * c0 + rs0;
        l1 = l1 * c1 + rs1;

        #pragma unroll
        for (int nt = 0; nt < 8; nt++) {
            oacc[nt][0] *= c0; oacc[nt][1] *= c0;
            oacc[nt][2] *= c1; oacc[nt][3] *= c1;
        }

        #pragma unroll
        for (int j = 0; j < 4; j++) {
            uint32_t pf[4];
            pf[0] = packh2(sacc[2 * j][0],     sacc[2 * j][1]);
            pf[1] = packh2(sacc[2 * j][2],     sacc[2 * j][3]);
            pf[2] = packh2(sacc[2 * j + 1][0], sacc[2 * j + 1][1]);
            pf[3] = packh2(sacc[2 * j + 1][2], sacc[2 * j + 1][3]);
            uint32_t vf[4][4];
            #pragma unroll
            for (int p = 0; p < 4; p++)
                ldsm4t(vf[p], vbase + 2 * ((j * 16 + b_row) * FHS
                                           + p * 16 + b_col));
            #pragma unroll
            for (int nt = 0; nt < 8; nt++)
                mma_f16(oacc[nt], pf, &vf[nt >> 1][(nt & 1) * 2]);
        }
        __syncthreads();
        buf ^= 1;
    }

    const float inv0 = 1.0f / l0;
    const float inv1 = 1.0f / l1;
    const int r0 = q0 + warp * 16 + lr;
    #pragma unroll
    for (int nt = 0; nt < 8; nt++) {
        const int d = nt * 8 + lc * 2;
        *(__half2*)(o + (size_t)r0 * CDIM + hd * HDIM + d) =
            __floats2half2_rn(oacc[nt][0] * inv0, oacc[nt][1] * inv0);
        *(__half2*)(o + (size_t)(r0 + 8) * CDIM + hd * HDIM + d) =
            __floats2half2_rn(oacc[nt][2] * inv1, oacc[nt][3] * inv1);
    }
}

// ---------------------------------------------------------------------------
// Launcher
// ---------------------------------------------------------------------------
extern "C" void kernel_launch(void* const* d_in, const int* in_sizes, int n_in,
                              void* d_out, int out_size)
{
    const float* x     = (const float*)d_in[0];
    const float* g1    = (const float*)d_in[1];
    const float* g2    = (const float*)d_in[2];
    const float* w_qkv = (const float*)d_in[3];
    const float* w_o   = (const float*)d_in[4];
    const float* w1    = (const float*)d_in[5];
    const float* w2    = (const float*)d_in[6];
    float* out = (float*)d_out;

    __half *h, *qkv, *o, *h2, *t;
    __half *wqkv_h, *wo_h, *w1_h, *w2_h;
    float *x1;
    cudaGetSymbolAddress((void**)&h,   g_h);
    cudaGetSymbolAddress((void**)&qkv, g_qkv);
    cudaGetSymbolAddress((void**)&o,   g_o);
    cudaGetSymbolAddress((void**)&x1,  g_x1);
    cudaGetSymbolAddress((void**)&h2,  g_h2);
    cudaGetSymbolAddress((void**)&t,   g_t);
    cudaGetSymbolAddress((void**)&wqkv_h, g_wqkv_h);
    cudaGetSymbolAddress((void**)&wo_h,   g_wo_h);
    cudaGetSymbolAddress((void**)&w1_h,   g_w1_h);
    cudaGetSymbolAddress((void**)&w2_h,   g_w2_h);

    cudaFuncSetAttribute(hgemm_kernel<1>,
        cudaFuncAttributeMaxDynamicSharedMemorySize, G_SMEM);
    cudaFuncSetAttribute(hgemm_kernel<2>,
        cudaFuncAttributeMaxDynamicSharedMemorySize, G_SMEM);
    cudaFuncSetAttribute(hgemm_kernel<3>,
        cudaFuncAttributeMaxDynamicSharedMemorySize, G_SMEM);

    // 0) all weights -> fp16 in one launch
    f2h_all_kernel<<<(N4_TOTAL + 255) / 256, 256>>>(
        w_qkv, w_o, w1, w2, wqkv_h, wo_h, w1_h, w2_h);

    // 1) h = rmsnorm(x, g1)
    rmsnorm_kernel<<<NTOK, 256>>>(x, g1, h);

    // 2) qkv = h @ w_qkv (q scaled by QSCALE = 0.125*log2e)
    hgemm_kernel<3><<<dim3(QKVDIM / 128, NTOK / 128), 256, G_SMEM>>>(
        h, wqkv_h, nullptr, qkv, NTOK, QKVDIM, CDIM);

    // 3) o = attention(qkv)
    flash_h_kernel<<<dim3(NTOK / 64, NHEAD), 128>>>(qkv, o);

    // 4) x1 = x + o @ w_o
    hgemm_kernel<1><<<dim3(CDIM / 128, NTOK / 128), 256, G_SMEM>>>(
        o, wo_h, x, x1, NTOK, CDIM, CDIM);

    // 5) h2 = rmsnorm(x1, g2)
    rmsnorm_kernel<<<NTOK, 256>>>(x1, g2, h2);

    // 6) t = gelu(h2 @ w1)
    hgemm_kernel<2><<<dim3(MDIM / 128, NTOK / 128), 256, G_SMEM>>>(
        h2, w1_h, nullptr, t, NTOK, MDIM, CDIM);

    // 7) out = x1 + t @ w2
    hgemm_kernel<1><<<dim3(CDIM / 128, NTOK / 128), 256, G_SMEM>>>(
        t, w2_h, x1, out, NTOK, CDIM, MDIM);
}

// round 14
// speedup vs baseline: 1.0679x; 1.0286x over previous
#include <cuda_runtime.h>
#include <cuda_fp16.h>
#include <cstdint>

// ---------------------------------------------------------------------------
// Problem constants
// ---------------------------------------------------------------------------
#define NTOK 4096
#define CDIM 1024
#define NHEAD 16
#define HDIM 64
#define MDIM 4096
#define QKVDIM 3072

// q pre-scale: (1/sqrt(64)) * log2(e)  -> softmax uses raw ex2
#define QSCALE 0.1803368801111204f

// ---------------------------------------------------------------------------
// Scratch (device globals — no allocations allowed)
// ---------------------------------------------------------------------------
__device__ __half g_h  [(size_t)NTOK * CDIM];
__device__ __half g_qkv[(size_t)NTOK * QKVDIM];   // q pre-scaled by QSCALE
__device__ __half g_o  [(size_t)NTOK * CDIM];
__device__ float  g_x1 [(size_t)NTOK * CDIM];
__device__ __half g_h2 [(size_t)NTOK * CDIM];
__device__ __half g_t  [(size_t)NTOK * MDIM];
__device__ __half g_wqkv_h[(size_t)CDIM * QKVDIM];
__device__ __half g_wo_h  [(size_t)CDIM * CDIM];
__device__ __half g_w1_h  [(size_t)CDIM * MDIM];
__device__ __half g_w2_h  [(size_t)MDIM * CDIM];

// ---------------------------------------------------------------------------
// Helpers
// ---------------------------------------------------------------------------
__device__ __forceinline__ float gelu_tanh(float x) {
    const float u = 0.7978845608028654f * (x + 0.044715f * x * x * x);
    return 0.5f * x * (1.0f + tanhf(u));
}
__device__ __forceinline__ float ex2f(float x) {
    float r;
    asm("ex2.approx.f32 %0, %1;" : "=f"(r) : "f"(x));
    return r;
}
__device__ __forceinline__ uint32_t ex2h2(uint32_t x) {
    uint32_t r;
    asm("ex2.approx.f16x2 %0, %1;" : "=r"(r) : "r"(x));
    return r;
}
__device__ __forceinline__ uint32_t packh2(float a, float b) {
    __half2 v = __floats2half2_rn(a, b);
    return *reinterpret_cast<uint32_t*>(&v);
}
__device__ __forceinline__ void mma_f16(float* c, const uint32_t* a,
                                        const uint32_t* b) {
    asm volatile(
        "mma.sync.aligned.m16n8k16.row.col.f32.f16.f16.f32 "
        "{%0,%1,%2,%3}, {%4,%5,%6,%7}, {%8,%9}, {%0,%1,%2,%3};"
        : "+f"(c[0]), "+f"(c[1]), "+f"(c[2]), "+f"(c[3])
        : "r"(a[0]), "r"(a[1]), "r"(a[2]), "r"(a[3]),
          "r"(b[0]), "r"(b[1]));
}
__device__ __forceinline__ void ldsm4(uint32_t* d, uint32_t a) {
    asm volatile("ldmatrix.sync.aligned.m8n8.x4.shared.b16 "
                 "{%0,%1,%2,%3}, [%4];"
                 : "=r"(d[0]), "=r"(d[1]), "=r"(d[2]), "=r"(d[3]) : "r"(a));
}
__device__ __forceinline__ void ldsm4t(uint32_t* d, uint32_t a) {
    asm volatile("ldmatrix.sync.aligned.m8n8.x4.trans.shared.b16 "
                 "{%0,%1,%2,%3}, [%4];"
                 : "=r"(d[0]), "=r"(d[1]), "=r"(d[2]), "=r"(d[3]) : "r"(a));
}
__device__ __forceinline__ void cp16(void* smem, const void* gmem) {
    uint32_t s = (uint32_t)__cvta_generic_to_shared(smem);
    asm volatile("cp.async.cg.shared.global [%0], [%1], 16;"
                 :: "r"(s), "l"(gmem));
}

// ---------------------------------------------------------------------------
// Fused fp32->fp16 conversion of ALL four weight matrices in one launch
// ---------------------------------------------------------------------------
#define N4_QKV ((CDIM * QKVDIM) / 4)
#define N4_WO  ((CDIM * CDIM) / 4)
#define N4_W1  ((CDIM * MDIM) / 4)
#define N4_W2  ((MDIM * CDIM) / 4)
#define N4_TOTAL (N4_QKV + N4_WO + N4_W1 + N4_W2)

__global__ __launch_bounds__(256) void f2h_all_kernel(
    const float* __restrict__ wqkv, const float* __restrict__ wo,
    const float* __restrict__ w1,   const float* __restrict__ w2,
    __half* __restrict__ dqkv, __half* __restrict__ dwo,
    __half* __restrict__ dw1,  __half* __restrict__ dw2)
{
    int i = blockIdx.x * 256 + threadIdx.x;
    if (i >= N4_TOTAL) return;
    const float* src;
    __half* dst;
    if (i < N4_QKV)                       { src = wqkv; dst = dqkv; }
    else if (i < N4_QKV + N4_WO)          { src = wo;  dst = dwo;  i -= N4_QKV; }
    else if (i < N4_QKV + N4_WO + N4_W1)  { src = w1;  dst = dw1;  i -= N4_QKV + N4_WO; }
    else                                  { src = w2;  dst = dw2;  i -= N4_QKV + N4_WO + N4_W1; }
    const float4 v = ((const float4*)src)[i];
    uint2 o;
    o.x = packh2(v.x, v.y);
    o.y = packh2(v.z, v.w);
    ((uint2*)dst)[i] = o;
}

// ---------------------------------------------------------------------------
// RMSNorm: one block per row, fp16 output
// ---------------------------------------------------------------------------
__global__ __launch_bounds__(256) void rmsnorm_kernel(
    const float* __restrict__ x, const float* __restrict__ g,
    __half* __restrict__ out)
{
    const int row = blockIdx.x;
    const int tid = threadIdx.x;
    const float4 v = ((const float4*)(x + (size_t)row * CDIM))[tid];
    float ss = v.x * v.x + v.y * v.y + v.z * v.z + v.w * v.w;
    #pragma unroll
    for (int o = 16; o; o >>= 1) ss += __shfl_xor_sync(0xffffffffu, ss, o);
    __shared__ float wsum[8];
    if ((tid & 31) == 0) wsum[tid >> 5] = ss;
    __syncthreads();
    float tot = wsum[0] + wsum[1] + wsum[2] + wsum[3]
              + wsum[4] + wsum[5] + wsum[6] + wsum[7];
    const float inv = rsqrtf(tot * (1.0f / (float)CDIM) + 1e-6f);
    const float4 gv = ((const float4*)g)[tid];
    uint2 o;
    o.x = packh2(v.x * inv * gv.x, v.y * inv * gv.y);
    o.y = packh2(v.z * inv * gv.z, v.w * inv * gv.w);
    ((uint2*)(out + (size_t)row * CDIM))[tid] = o;
}

// ---------------------------------------------------------------------------
// FP16 GEMM (R8/R13-proven): 128x128x32 tile, 8 warps (warp 64x32),
// mma.m16n8k16, ldmatrix, 3-stage cp.async pipeline, 256 threads.
// MODE 1: float C = acc + R
// MODE 2: half  C = gelu(acc)
// MODE 3: half  C = acc * (col<CDIM ? QSCALE : 1)
// ---------------------------------------------------------------------------
#define AHS 40    // A smem row stride (halves): 32 + 8 pad
#define BHS 136   // B smem row stride (halves): 128 + 8 pad
#define A_STAGE (128 * AHS)
#define B_STAGE (32 * BHS)
#define G_SMEM (3 * (A_STAGE + B_STAGE) * 2)

template <int MODE>
__global__ __launch_bounds__(256) void hgemm_kernel(
    const __half* __restrict__ A, const __half* __restrict__ B,
    const float* __restrict__ R, void* __restrict__ Cv,
    int M, int N, int K)
{
    extern __shared__ __half dsm[];
    __half* Asm = dsm;
    __half* Bsm = dsm + 3 * A_STAGE;

    const int tid  = threadIdx.x;
    const int bm   = blockIdx.y * 128;
    const int bn   = blockIdx.x * 128;
    const int warp = tid >> 5;
    const int lane = tid & 31;
    const int wm   = (warp >> 2) << 6;   // 0 / 64
    const int wn   = (warp & 3) << 5;    // 0,32,64,96
    const int lr   = lane >> 2;
    const int lc   = lane & 3;

    float acc[4][4][4];
    #pragma unroll
    for (int mt = 0; mt < 4; mt++)
        #pragma unroll
        for (int nt = 0; nt < 4; nt++)
            #pragma unroll
            for (int i = 0; i < 4; i++) acc[mt][nt][i] = 0.0f;

    auto prefetch = [&](int st, int k0) {
        __half* Ad = Asm + st * A_STAGE;
        __half* Bd = Bsm + st * B_STAGE;
        #pragma unroll
        for (int r = 0; r < 2; r++) {
            const int c  = tid + (r << 8);          // 0..511
            const int am = c >> 2;                   // 0..127
            const int ak = (c & 3) << 3;             // 0,8,16,24
            cp16(&Ad[am * AHS + ak],
                 A + (size_t)(bm + am) * K + k0 + ak);
            const int bk = c >> 4;                   // 0..31
            const int bq = (c & 15) << 3;            // 0..120
            cp16(&Bd[bk * BHS + bq],
                 B + (size_t)(k0 + bk) * N + bn + bq);
        }
        asm volatile("cp.async.commit_group;");
    };

    prefetch(0, 0);
    prefetch(1, 32);

    const int a_row = lane & 15;
    const int a_hi  = (lane >> 4) << 3;
    const int b_row = (lane & 7) + ((lane >> 3) & 1) * 8;
    const int b_col = (lane >> 4) << 3;

    int buf = 0;
    for (int k0 = 0; k0 < K; k0 += 32) {
        if (k0 + 32 < K)
            asm volatile("cp.async.wait_group 1;");
        else
            asm volatile("cp.async.wait_group 0;");
        __syncthreads();
        if (k0 + 64 < K) {
            int nst = buf + 2; if (nst >= 3) nst -= 3;
            prefetch(nst, k0 + 64);
        }

        const uint32_t abase =
            (uint32_t)__cvta_generic_to_shared(Asm + buf * A_STAGE);
        const uint32_t bbase =
            (uint32_t)__cvta_generic_to_shared(Bsm + buf * B_STAGE);

        #pragma unroll
        for (int ks = 0; ks < 2; ks++) {
            uint32_t af[4][4], bf[2][4];
            #pragma unroll
            for (int mt = 0; mt < 4; mt++)
                ldsm4(af[mt], abase + 2 * ((wm + mt * 16 + a_row) * AHS
                                           + ks * 16 + a_hi));
            #pragma unroll
            for (int p = 0; p < 2; p++)
                ldsm4t(bf[p], bbase + 2 * ((ks * 16 + b_row) * BHS
                                           + wn + p * 16 + b_col));
            #pragma unroll
            for (int mt = 0; mt < 4; mt++)
                #pragma unroll
                for (int nt = 0; nt < 4; nt++)
                    mma_f16(acc[mt][nt], af[mt], &bf[nt >> 1][(nt & 1) * 2]);
        }
        buf++; if (buf >= 3) buf -= 3;
    }

    #pragma unroll
    for (int mt = 0; mt < 4; mt++) {
        const int row0 = bm + wm + mt * 16 + lr;
        #pragma unroll
        for (int nt = 0; nt < 4; nt++) {
            const int col = bn + wn + nt * 8 + lc * 2;
            #pragma unroll
            for (int half_ = 0; half_ < 2; half_++) {
                const size_t row = (size_t)(row0 + half_ * 8);
                float vx = acc[mt][nt][half_ * 2];
                float vy = acc[mt][nt][half_ * 2 + 1];
                if (MODE == 1) {
                    const float2 r2 = *(const float2*)(R + row * N + col);
                    float* C = (float*)Cv;
                    *(float2*)(C + row * N + col) =
                        make_float2(vx + r2.x, vy + r2.y);
                } else if (MODE == 2) {
                    __half* C = (__half*)Cv;
                    *(__half2*)(C + row * N + col) =
                        __floats2half2_rn(gelu_tanh(vx), gelu_tanh(vy));
                } else {
                    const float s = (col < CDIM) ? QSCALE : 1.0f;
                    __half* C = (__half*)Cv;
                    *(__half2*)(C + row * N + col) =
                        __floats2half2_rn(vx * s, vy * s);
                }
            }
        }
    }
}

// ---------------------------------------------------------------------------
// FP16 flash attention: 128 threads (4 warps), 64 queries/CTA, 64-key tiles,
// double-buffered K/V, register-repacked P. Scores in log2 domain.
// Exps computed in fp16x2 (half the MUFU ops); row-sum l accumulated via an
// extra mma against a constant all-ones B fragment (no rs reduction).
// Single barrier per key tile (the top-of-loop barrier covers buffer reuse).
// ---------------------------------------------------------------------------
#define FHS 72   // smem row stride (halves): 64 + 8 pad

__global__ __launch_bounds__(128) void flash_h_kernel(
    const __half* __restrict__ qkv, __half* __restrict__ o)
{
    __shared__ __half Qs[64 * FHS];
    __shared__ __half Ks[2][64 * FHS];
    __shared__ __half Vs[2][64 * FHS];

    const int tid  = threadIdx.x;
    const int warp = tid >> 5;
    const int lane = tid & 31;
    const int lr   = lane >> 2;
    const int lc   = lane & 3;
    const int hd   = blockIdx.y;
    const int q0   = blockIdx.x * 64;

    #pragma unroll
    for (int s = 0; s < 4; s++) {
        const int c  = tid + s * 128;
        const int r  = c >> 3;
        const int cq = (c & 7) << 3;
        *(uint4*)(Qs + r * FHS + cq) =
            *(const uint4*)(qkv + (size_t)(q0 + r) * QKVDIM
                            + hd * HDIM + cq);
    }

    auto prefetch = [&](int buf, int k0) {
        const __half* Kp = qkv + (size_t)k0 * QKVDIM + CDIM + hd * HDIM;
        const __half* Vp = Kp + CDIM;
        #pragma unroll
        for (int s = 0; s < 4; s++) {
            const int c  = tid + s * 128;
            const int r  = c >> 3;
            const int cq = (c & 7) << 3;
            cp16(&Ks[buf][r * FHS + cq], Kp + (size_t)r * QKVDIM + cq);
            cp16(&Vs[buf][r * FHS + cq], Vp + (size_t)r * QKVDIM + cq);
        }
        asm volatile("cp.async.commit_group;");
    };

    prefetch(0, 0);
    __syncthreads();

    uint32_t qf[4][4];
    {
        const uint32_t qbase = (uint32_t)__cvta_generic_to_shared(Qs);
        const int a_row = warp * 16 + (lane & 15);
        const int a_hi  = (lane >> 4) << 3;
        #pragma unroll
        for (int j = 0; j < 4; j++)
            ldsm4(qf[j], qbase + 2 * (a_row * FHS + j * 16 + a_hi));
    }

    float m0 = -1e30f, m1 = -1e30f;
    float oacc[8][4];
    float lacc[4];
    #pragma unroll
    for (int nt = 0; nt < 8; nt++)
        #pragma unroll
        for (int i = 0; i < 4; i++) oacc[nt][i] = 0.0f;
    #pragma unroll
    for (int i = 0; i < 4; i++) lacc[i] = 0.0f;

    const uint32_t onesb[2] = {0x3C003C00u, 0x3C003C00u};   // 1.0h x4

    const int b_row = (lane & 7) + ((lane >> 3) & 1) * 8;
    const int b_col = (lane >> 4) << 3;
    const int k_row = lane & 7;
    const int k_r2  = ((lane >> 4) & 1) * 8;
    const int k_col = ((lane >> 3) & 1) * 8;

    int buf = 0;
    for (int kt = 0; kt < NTOK / 64; kt++) {
        asm volatile("cp.async.wait_group 0;");
        __syncthreads();      // also proves all warps done with buf's prior use
        if (kt + 1 < NTOK / 64) prefetch(buf ^ 1, (kt + 1) * 64);

        const uint32_t kbase =
            (uint32_t)__cvta_generic_to_shared(&Ks[buf][0]);
        const uint32_t vbase =
            (uint32_t)__cvta_generic_to_shared(&Vs[buf][0]);

        // --- S = Q K^T ---
        float sacc[8][4];
        #pragma unroll
        for (int nt = 0; nt < 8; nt++)
            #pragma unroll
            for (int i = 0; i < 4; i++) sacc[nt][i] = 0.0f;

        #pragma unroll
        for (int j = 0; j < 4; j++) {
            uint32_t kf[4][4];
            #pragma unroll
            for (int p = 0; p < 4; p++)
                ldsm4(kf[p], kbase + 2 * ((p * 16 + k_row + k_r2) * FHS
                                          + j * 16 + k_col));
            #pragma unroll
            for (int nt = 0; nt < 8; nt++)
                mma_f16(sacc[nt], qf[j], &kf[nt >> 1][(nt & 1) * 2]);
        }

        // --- running max (f32) ---
        float mx0 = -1e30f, mx1 = -1e30f;
        #pragma unroll
        for (int nt = 0; nt < 8; nt++) {
            mx0 = fmaxf(mx0, fmaxf(sacc[nt][0], sacc[nt][1]));
            mx1 = fmaxf(mx1, fmaxf(sacc[nt][2], sacc[nt][3]));
        }
        mx0 = fmaxf(mx0, __shfl_xor_sync(0xffffffffu, mx0, 1));
        mx0 = fmaxf(mx0, __shfl_xor_sync(0xffffffffu, mx0, 2));
        mx1 = fmaxf(mx1, __shfl_xor_sync(0xffffffffu, mx1, 1));
        mx1 = fmaxf(mx1, __shfl_xor_sync(0xffffffffu, mx1, 2));

        const float mn0 = fmaxf(m0, mx0);
        const float mn1 = fmaxf(m1, mx1);
        const float c0 = ex2f(m0 - mn0);
        const float c1 = ex2f(m1 - mn1);
        m0 = mn0; m1 = mn1;

        // rescale running accumulators (l behaves exactly like an O column)
        lacc[0] *= c0; lacc[1] *= c0; lacc[2] *= c1; lacc[3] *= c1;
        #pragma unroll
        for (int nt = 0; nt < 8; nt++) {
            oacc[nt][0] *= c0; oacc[nt][1] *= c0;
            oacc[nt][2] *= c1; oacc[nt][3] *= c1;
        }

        // --- P (fp16x2 exps) ; O += P V ; l += P @ ones ---
        #pragma unroll
        for (int j = 0; j < 4; j++) {
            uint32_t pf[4];
            pf[0] = ex2h2(packh2(sacc[2 * j][0] - mn0,
                                 sacc[2 * j][1] - mn0));
            pf[1] = ex2h2(packh2(sacc[2 * j][2] - mn1,
                                 sacc[2 * j][3] - mn1));
            pf[2] = ex2h2(packh2(sacc[2 * j + 1][0] - mn0,
                                 sacc[2 * j + 1][1] - mn0));
            pf[3] = ex2h2(packh2(sacc[2 * j + 1][2] - mn1,
                                 sacc[2 * j + 1][3] - mn1));
            mma_f16(lacc, pf, onesb);
            uint32_t vf[4][4];
            #pragma unroll
            for (int p = 0; p < 4; p++)
                ldsm4t(vf[p], vbase + 2 * ((j * 16 + b_row) * FHS
                                           + p * 16 + b_col));
            #pragma unroll
            for (int nt = 0; nt < 8; nt++)
                mma_f16(oacc[nt], pf, &vf[nt >> 1][(nt & 1) * 2]);
        }
        buf ^= 1;
    }

    const float inv0 = 1.0f / lacc[0];
    const float inv1 = 1.0f / lacc[2];
    const int r0 = q0 + warp * 16 + lr;
    #pragma unroll
    for (int nt = 0; nt < 8; nt++) {
        const int d = nt * 8 + lc * 2;
        *(__half2*)(o + (size_t)r0 * CDIM + hd * HDIM + d) =
            __floats2half2_rn(oacc[nt][0] * inv0, oacc[nt][1] * inv0);
        *(__half2*)(o + (size_t)(r0 + 8) * CDIM + hd * HDIM + d) =
            __floats2half2_rn(oacc[nt][2] * inv1, oacc[nt][3] * inv1);
    }
}

// ---------------------------------------------------------------------------
// Launcher
// ---------------------------------------------------------------------------
extern "C" void kernel_launch(void* const* d_in, const int* in_sizes, int n_in,
                              void* d_out, int out_size)
{
    const float* x     = (const float*)d_in[0];
    const float* g1    = (const float*)d_in[1];
    const float* g2    = (const float*)d_in[2];
    const float* w_qkv = (const float*)d_in[3];
    const float* w_o   = (const float*)d_in[4];
    const float* w1    = (const float*)d_in[5];
    const float* w2    = (const float*)d_in[6];
    float* out = (float*)d_out;

    __half *h, *qkv, *o, *h2, *t;
    __half *wqkv_h, *wo_h, *w1_h, *w2_h;
    float *x1;
    cudaGetSymbolAddress((void**)&h,   g_h);
    cudaGetSymbolAddress((void**)&qkv, g_qkv);
    cudaGetSymbolAddress((void**)&o,   g_o);
    cudaGetSymbolAddress((void**)&x1,  g_x1);
    cudaGetSymbolAddress((void**)&h2,  g_h2);
    cudaGetSymbolAddress((void**)&t,   g_t);
    cudaGetSymbolAddress((void**)&wqkv_h, g_wqkv_h);
    cudaGetSymbolAddress((void**)&wo_h,   g_wo_h);
    cudaGetSymbolAddress((void**)&w1_h,   g_w1_h);
    cudaGetSymbolAddress((void**)&w2_h,   g_w2_h);

    cudaFuncSetAttribute(hgemm_kernel<1>,
        cudaFuncAttributeMaxDynamicSharedMemorySize, G_SMEM);
    cudaFuncSetAttribute(hgemm_kernel<2>,
        cudaFuncAttributeMaxDynamicSharedMemorySize, G_SMEM);
    cudaFuncSetAttribute(hgemm_kernel<3>,
        cudaFuncAttributeMaxDynamicSharedMemorySize, G_SMEM);

    // 0) all weights -> fp16 in one launch
    f2h_all_kernel<<<(N4_TOTAL + 255) / 256, 256>>>(
        w_qkv, w_o, w1, w2, wqkv_h, wo_h, w1_h, w2_h);

    // 1) h = rmsnorm(x, g1)
    rmsnorm_kernel<<<NTOK, 256>>>(x, g1, h);

    // 2) qkv = h @ w_qkv (q scaled by QSCALE = 0.125*log2e)
    hgemm_kernel<3><<<dim3(QKVDIM / 128, NTOK / 128), 256, G_SMEM>>>(
        h, wqkv_h, nullptr, qkv, NTOK, QKVDIM, CDIM);

    // 3) o = attention(qkv)
    flash_h_kernel<<<dim3(NTOK / 64, NHEAD), 128>>>(qkv, o);

    // 4) x1 = x + o @ w_o
    hgemm_kernel<1><<<dim3(CDIM / 128, NTOK / 128), 256, G_SMEM>>>(
        o, wo_h, x, x1, NTOK, CDIM, CDIM);

    // 5) h2 = rmsnorm(x1, g2)
    rmsnorm_kernel<<<NTOK, 256>>>(x1, g2, h2);

    // 6) t = gelu(h2 @ w1)
    hgemm_kernel<2><<<dim3(MDIM / 128, NTOK / 128), 256, G_SMEM>>>(
        h2, w1_h, nullptr, t, NTOK, MDIM, CDIM);

    // 7) out = x1 + t @ w2
    hgemm_kernel<1><<<dim3(CDIM / 128, NTOK / 128), 256, G_SMEM>>>(
        t, w2_h, x1, out, NTOK, CDIM, MDIM);
}

// round 17
// speedup vs baseline: 1.0693x; 1.0013x over previous
#include <cuda_runtime.h>
#include <cuda_fp16.h>
#include <cstdint>

// ---------------------------------------------------------------------------
// Problem constants
// ---------------------------------------------------------------------------
#define NTOK 4096
#define CDIM 1024
#define NHEAD 16
#define HDIM 64
#define MDIM 4096
#define QKVDIM 3072

// q pre-scale: (1/sqrt(64)) * log2(e)  -> softmax uses raw ex2
#define QSCALE 0.1803368801111204f

// ---------------------------------------------------------------------------
// Scratch (device globals — no allocations allowed)
// ---------------------------------------------------------------------------
__device__ __half g_h  [(size_t)NTOK * CDIM];
__device__ __half g_qkv[(size_t)NTOK * QKVDIM];   // q pre-scaled by QSCALE
__device__ __half g_o  [(size_t)NTOK * CDIM];
__device__ float  g_x1 [(size_t)NTOK * CDIM];
__device__ __half g_h2 [(size_t)NTOK * CDIM];
__device__ __half g_t  [(size_t)NTOK * MDIM];
__device__ __half g_wqkv_h[(size_t)CDIM * QKVDIM];
__device__ __half g_wo_h  [(size_t)CDIM * CDIM];
__device__ __half g_w1_h  [(size_t)CDIM * MDIM];
__device__ __half g_w2_h  [(size_t)MDIM * CDIM];

// ---------------------------------------------------------------------------
// Helpers
// ---------------------------------------------------------------------------
__device__ __forceinline__ float gelu_tanh(float x) {
    const float u = 0.7978845608028654f * (x + 0.044715f * x * x * x);
    return 0.5f * x * (1.0f + tanhf(u));
}
__device__ __forceinline__ float ex2f(float x) {
    float r;
    asm("ex2.approx.f32 %0, %1;" : "=f"(r) : "f"(x));
    return r;
}
__device__ __forceinline__ uint32_t ex2h2(uint32_t x) {
    uint32_t r;
    asm("ex2.approx.f16x2 %0, %1;" : "=r"(r) : "r"(x));
    return r;
}
__device__ __forceinline__ uint32_t packh2(float a, float b) {
    __half2 v = __floats2half2_rn(a, b);
    return *reinterpret_cast<uint32_t*>(&v);
}
__device__ __forceinline__ void mma_f16(float* c, const uint32_t* a,
                                        const uint32_t* b) {
    asm volatile(
        "mma.sync.aligned.m16n8k16.row.col.f32.f16.f16.f32 "
        "{%0,%1,%2,%3}, {%4,%5,%6,%7}, {%8,%9}, {%0,%1,%2,%3};"
        : "+f"(c[0]), "+f"(c[1]), "+f"(c[2]), "+f"(c[3])
        : "r"(a[0]), "r"(a[1]), "r"(a[2]), "r"(a[3]),
          "r"(b[0]), "r"(b[1]));
}
__device__ __forceinline__ void ldsm4(uint32_t* d, uint32_t a) {
    asm volatile("ldmatrix.sync.aligned.m8n8.x4.shared.b16 "
                 "{%0,%1,%2,%3}, [%4];"
                 : "=r"(d[0]), "=r"(d[1]), "=r"(d[2]), "=r"(d[3]) : "r"(a));
}
__device__ __forceinline__ void ldsm4t(uint32_t* d, uint32_t a) {
    asm volatile("ldmatrix.sync.aligned.m8n8.x4.trans.shared.b16 "
                 "{%0,%1,%2,%3}, [%4];"
                 : "=r"(d[0]), "=r"(d[1]), "=r"(d[2]), "=r"(d[3]) : "r"(a));
}
__device__ __forceinline__ void cp16(void* smem, const void* gmem) {
    uint32_t s = (uint32_t)__cvta_generic_to_shared(smem);
    asm volatile("cp.async.cg.shared.global [%0], [%1], 16;"
                 :: "r"(s), "l"(gmem));
}

// ---------------------------------------------------------------------------
// Fused fp32->fp16 conversion of ALL four weight matrices in one launch
// ---------------------------------------------------------------------------
#define N4_QKV ((CDIM * QKVDIM) / 4)
#define N4_WO  ((CDIM * CDIM) / 4)
#define N4_W1  ((CDIM * MDIM) / 4)
#define N4_W2  ((MDIM * CDIM) / 4)
#define N4_TOTAL (N4_QKV + N4_WO + N4_W1 + N4_W2)

__global__ __launch_bounds__(256) void f2h_all_kernel(
    const float* __restrict__ wqkv, const float* __restrict__ wo,
    const float* __restrict__ w1,   const float* __restrict__ w2,
    __half* __restrict__ dqkv, __half* __restrict__ dwo,
    __half* __restrict__ dw1,  __half* __restrict__ dw2)
{
    int i = blockIdx.x * 256 + threadIdx.x;
    if (i >= N4_TOTAL) return;
    const float* src;
    __half* dst;
    if (i < N4_QKV)                       { src = wqkv; dst = dqkv; }
    else if (i < N4_QKV + N4_WO)          { src = wo;  dst = dwo;  i -= N4_QKV; }
    else if (i < N4_QKV + N4_WO + N4_W1)  { src = w1;  dst = dw1;  i -= N4_QKV + N4_WO; }
    else                                  { src = w2;  dst = dw2;  i -= N4_QKV + N4_WO + N4_W1; }
    const float4 v = ((const float4*)src)[i];
    uint2 o;
    o.x = packh2(v.x, v.y);
    o.y = packh2(v.z, v.w);
    ((uint2*)dst)[i] = o;
}

// ---------------------------------------------------------------------------
// RMSNorm: one block per row, fp16 output
// ---------------------------------------------------------------------------
__global__ __launch_bounds__(256) void rmsnorm_kernel(
    const float* __restrict__ x, const float* __restrict__ g,
    __half* __restrict__ out)
{
    const int row = blockIdx.x;
    const int tid = threadIdx.x;
    const float4 v = ((const float4*)(x + (size_t)row * CDIM))[tid];
    float ss = v.x * v.x + v.y * v.y + v.z * v.z + v.w * v.w;
    #pragma unroll
    for (int o = 16; o; o >>= 1) ss += __shfl_xor_sync(0xffffffffu, ss, o);
    __shared__ float wsum[8];
    if ((tid & 31) == 0) wsum[tid >> 5] = ss;
    __syncthreads();
    float tot = wsum[0] + wsum[1] + wsum[2] + wsum[3]
              + wsum[4] + wsum[5] + wsum[6] + wsum[7];
    const float inv = rsqrtf(tot * (1.0f / (float)CDIM) + 1e-6f);
    const float4 gv = ((const float4*)g)[tid];
    uint2 o;
    o.x = packh2(v.x * inv * gv.x, v.y * inv * gv.y);
    o.y = packh2(v.z * inv * gv.z, v.w * inv * gv.w);
    ((uint2*)(out + (size_t)row * CDIM))[tid] = o;
}

// ---------------------------------------------------------------------------
// FP16 GEMM (R8/R13-proven): 128x128x32 tile, 8 warps (warp 64x32),
// mma.m16n8k16, ldmatrix, 3-stage cp.async pipeline, 256 threads.
// MODE 1: float C = acc + R
// MODE 2: half  C = gelu(acc)
// MODE 3: half  C = acc * (col<CDIM ? QSCALE : 1)
// ---------------------------------------------------------------------------
#define AHS 40    // A smem row stride (halves): 32 + 8 pad
#define BHS 136   // B smem row stride (halves): 128 + 8 pad
#define A_STAGE (128 * AHS)
#define B_STAGE (32 * BHS)
#define G_SMEM (3 * (A_STAGE + B_STAGE) * 2)

template <int MODE>
__global__ __launch_bounds__(256) void hgemm_kernel(
    const __half* __restrict__ A, const __half* __restrict__ B,
    const float* __restrict__ R, void* __restrict__ Cv,
    int M, int N, int K)
{
    extern __shared__ __half dsm[];
    __half* Asm = dsm;
    __half* Bsm = dsm + 3 * A_STAGE;

    const int tid  = threadIdx.x;
    const int bm   = blockIdx.y * 128;
    const int bn   = blockIdx.x * 128;
    const int warp = tid >> 5;
    const int lane = tid & 31;
    const int wm   = (warp >> 2) << 6;   // 0 / 64
    const int wn   = (warp & 3) << 5;    // 0,32,64,96
    const int lr   = lane >> 2;
    const int lc   = lane & 3;

    float acc[4][4][4];
    #pragma unroll
    for (int mt = 0; mt < 4; mt++)
        #pragma unroll
        for (int nt = 0; nt < 4; nt++)
            #pragma unroll
            for (int i = 0; i < 4; i++) acc[mt][nt][i] = 0.0f;

    auto prefetch = [&](int st, int k0) {
        __half* Ad = Asm + st * A_STAGE;
        __half* Bd = Bsm + st * B_STAGE;
        #pragma unroll
        for (int r = 0; r < 2; r++) {
            const int c  = tid + (r << 8);          // 0..511
            const int am = c >> 2;                   // 0..127
            const int ak = (c & 3) << 3;             // 0,8,16,24
            cp16(&Ad[am * AHS + ak],
                 A + (size_t)(bm + am) * K + k0 + ak);
            const int bk = c >> 4;                   // 0..31
            const int bq = (c & 15) << 3;            // 0..120
            cp16(&Bd[bk * BHS + bq],
                 B + (size_t)(k0 + bk) * N + bn + bq);
        }
        asm volatile("cp.async.commit_group;");
    };

    prefetch(0, 0);
    prefetch(1, 32);

    const int a_row = lane & 15;
    const int a_hi  = (lane >> 4) << 3;
    const int b_row = (lane & 7) + ((lane >> 3) & 1) * 8;
    const int b_col = (lane >> 4) << 3;

    int buf = 0;
    for (int k0 = 0; k0 < K; k0 += 32) {
        if (k0 + 32 < K)
            asm volatile("cp.async.wait_group 1;");
        else
            asm volatile("cp.async.wait_group 0;");
        __syncthreads();
        if (k0 + 64 < K) {
            int nst = buf + 2; if (nst >= 3) nst -= 3;
            prefetch(nst, k0 + 64);
        }

        const uint32_t abase =
            (uint32_t)__cvta_generic_to_shared(Asm + buf * A_STAGE);
        const uint32_t bbase =
            (uint32_t)__cvta_generic_to_shared(Bsm + buf * B_STAGE);

        #pragma unroll
        for (int ks = 0; ks < 2; ks++) {
            uint32_t af[4][4], bf[2][4];
            #pragma unroll
            for (int mt = 0; mt < 4; mt++)
                ldsm4(af[mt], abase + 2 * ((wm + mt * 16 + a_row) * AHS
                                           + ks * 16 + a_hi));
            #pragma unroll
            for (int p = 0; p < 2; p++)
                ldsm4t(bf[p], bbase + 2 * ((ks * 16 + b_row) * BHS
                                           + wn + p * 16 + b_col));
            #pragma unroll
            for (int mt = 0; mt < 4; mt++)
                #pragma unroll
                for (int nt = 0; nt < 4; nt++)
                    mma_f16(acc[mt][nt], af[mt], &bf[nt >> 1][(nt & 1) * 2]);
        }
        buf++; if (buf >= 3) buf -= 3;
    }

    #pragma unroll
    for (int mt = 0; mt < 4; mt++) {
        const int row0 = bm + wm + mt * 16 + lr;
        #pragma unroll
        for (int nt = 0; nt < 4; nt++) {
            const int col = bn + wn + nt * 8 + lc * 2;
            #pragma unroll
            for (int half_ = 0; half_ < 2; half_++) {
                const size_t row = (size_t)(row0 + half_ * 8);
                float vx = acc[mt][nt][half_ * 2];
                float vy = acc[mt][nt][half_ * 2 + 1];
                if (MODE == 1) {
                    const float2 r2 = *(const float2*)(R + row * N + col);
                    float* C = (float*)Cv;
                    *(float2*)(C + row * N + col) =
                        make_float2(vx + r2.x, vy + r2.y);
                } else if (MODE == 2) {
                    __half* C = (__half*)Cv;
                    *(__half2*)(C + row * N + col) =
                        __floats2half2_rn(gelu_tanh(vx), gelu_tanh(vy));
                } else {
                    const float s = (col < CDIM) ? QSCALE : 1.0f;
                    __half* C = (__half*)Cv;
                    *(__half2*)(C + row * N + col) =
                        __floats2half2_rn(vx * s, vy * s);
                }
            }
        }
    }
}

// ---------------------------------------------------------------------------
// FP16 flash attention (R14-proven): 128 threads (4 warps), 64 queries/CTA,
// 64-key tiles, double-buffered K/V, register-repacked P, fp16x2 exps,
// mma-accumulated row sums, single barrier per key tile.
// ---------------------------------------------------------------------------
#define FHS 72   // smem row stride (halves): 64 + 8 pad

__global__ __launch_bounds__(128) void flash_h_kernel(
    const __half* __restrict__ qkv, __half* __restrict__ o)
{
    __shared__ __half Qs[64 * FHS];
    __shared__ __half Ks[2][64 * FHS];
    __shared__ __half Vs[2][64 * FHS];

    const int tid  = threadIdx.x;
    const int warp = tid >> 5;
    const int lane = tid & 31;
    const int lr   = lane >> 2;
    const int lc   = lane & 3;
    const int hd   = blockIdx.y;
    const int q0   = blockIdx.x * 64;

    #pragma unroll
    for (int s = 0; s < 4; s++) {
        const int c  = tid + s * 128;
        const int r  = c >> 3;
        const int cq = (c & 7) << 3;
        *(uint4*)(Qs + r * FHS + cq) =
            *(const uint4*)(qkv + (size_t)(q0 + r) * QKVDIM
                            + hd * HDIM + cq);
    }

    auto prefetch = [&](int buf, int k0) {
        const __half* Kp = qkv + (size_t)k0 * QKVDIM + CDIM + hd * HDIM;
        const __half* Vp = Kp + CDIM;
        #pragma unroll
        for (int s = 0; s < 4; s++) {
            const int c  = tid + s * 128;
            const int r  = c >> 3;
            const int cq = (c & 7) << 3;
            cp16(&Ks[buf][r * FHS + cq], Kp + (size_t)r * QKVDIM + cq);
            cp16(&Vs[buf][r * FHS + cq], Vp + (size_t)r * QKVDIM + cq);
        }
        asm volatile("cp.async.commit_group;");
    };

    prefetch(0, 0);
    __syncthreads();

    uint32_t qf[4][4];
    {
        const uint32_t qbase = (uint32_t)__cvta_generic_to_shared(Qs);
        const int a_row = warp * 16 + (lane & 15);
        const int a_hi  = (lane >> 4) << 3;
        #pragma unroll
        for (int j = 0; j < 4; j++)
            ldsm4(qf[j], qbase + 2 * (a_row * FHS + j * 16 + a_hi));
    }

    float m0 = -1e30f, m1 = -1e30f;
    float oacc[8][4];
    float lacc[4];
    #pragma unroll
    for (int nt = 0; nt < 8; nt++)
        #pragma unroll
        for (int i = 0; i < 4; i++) oacc[nt][i] = 0.0f;
    #pragma unroll
    for (int i = 0; i < 4; i++) lacc[i] = 0.0f;

    const uint32_t onesb[2] = {0x3C003C00u, 0x3C003C00u};   // 1.0h x4

    const int b_row = (lane & 7) + ((lane >> 3) & 1) * 8;
    const int b_col = (lane >> 4) << 3;
    const int k_row = lane & 7;
    const int k_r2  = ((lane >> 4) & 1) * 8;
    const int k_col = ((lane >> 3) & 1) * 8;

    int buf = 0;
    for (int kt = 0; kt < NTOK / 64; kt++) {
        asm volatile("cp.async.wait_group 0;");
        __syncthreads();
        if (kt + 1 < NTOK / 64) prefetch(buf ^ 1, (kt + 1) * 64);

        const uint32_t kbase =
            (uint32_t)__cvta_generic_to_shared(&Ks[buf][0]);
        const uint32_t vbase =
            (uint32_t)__cvta_generic_to_shared(&Vs[buf][0]);

        float sacc[8][4];
        #pragma unroll
        for (int nt = 0; nt < 8; nt++)
            #pragma unroll
            for (int i = 0; i < 4; i++) sacc[nt][i] = 0.0f;

        #pragma unroll
        for (int j = 0; j < 4; j++) {
            uint32_t kf[4][4];
            #pragma unroll
            for (int p = 0; p < 4; p++)
                ldsm4(kf[p], kbase + 2 * ((p * 16 + k_row + k_r2) * FHS
                                          + j * 16 + k_col));
            #pragma unroll
            for (int nt = 0; nt < 8; nt++)
                mma_f16(sacc[nt], qf[j], &kf[nt >> 1][(nt & 1) * 2]);
        }

        float mx0 = -1e30f, mx1 = -1e30f;
        #pragma unroll
        for (int nt = 0; nt < 8; nt++) {
            mx0 = fmaxf(mx0, fmaxf(sacc[nt][0], sacc[nt][1]));
            mx1 = fmaxf(mx1, fmaxf(sacc[nt][2], sacc[nt][3]));
        }
        mx0 = fmaxf(mx0, __shfl_xor_sync(0xffffffffu, mx0, 1));
        mx0 = fmaxf(mx0, __shfl_xor_sync(0xffffffffu, mx0, 2));
        mx1 = fmaxf(mx1, __shfl_xor_sync(0xffffffffu, mx1, 1));
        mx1 = fmaxf(mx1, __shfl_xor_sync(0xffffffffu, mx1, 2));

        const float mn0 = fmaxf(m0, mx0);
        const float mn1 = fmaxf(m1, mx1);
        const float c0 = ex2f(m0 - mn0);
        const float c1 = ex2f(m1 - mn1);
        m0 = mn0; m1 = mn1;

        lacc[0] *= c0; lacc[1] *= c0; lacc[2] *= c1; lacc[3] *= c1;
        #pragma unroll
        for (int nt = 0; nt < 8; nt++) {
            oacc[nt][0] *= c0; oacc[nt][1] *= c0;
            oacc[nt][2] *= c1; oacc[nt][3] *= c1;
        }

        #pragma unroll
        for (int j = 0; j < 4; j++) {
            uint32_t pf[4];
            pf[0] = ex2h2(packh2(sacc[2 * j][0] - mn0,
                                 sacc[2 * j][1] - mn0));
            pf[1] = ex2h2(packh2(sacc[2 * j][2] - mn1,
                                 sacc[2 * j][3] - mn1));
            pf[2] = ex2h2(packh2(sacc[2 * j + 1][0] - mn0,
                                 sacc[2 * j + 1][1] - mn0));
            pf[3] = ex2h2(packh2(sacc[2 * j + 1][2] - mn1,
                                 sacc[2 * j + 1][3] - mn1));
            mma_f16(lacc, pf, onesb);
            uint32_t vf[4][4];
            #pragma unroll
            for (int p = 0; p < 4; p++)
                ldsm4t(vf[p], vbase + 2 * ((j * 16 + b_row) * FHS
                                           + p * 16 + b_col));
            #pragma unroll
            for (int nt = 0; nt < 8; nt++)
                mma_f16(oacc[nt], pf, &vf[nt >> 1][(nt & 1) * 2]);
        }
        buf ^= 1;
    }

    const float inv0 = 1.0f / lacc[0];
    const float inv1 = 1.0f / lacc[2];
    const int r0 = q0 + warp * 16 + lr;
    #pragma unroll
    for (int nt = 0; nt < 8; nt++) {
        const int d = nt * 8 + lc * 2;
        *(__half2*)(o + (size_t)r0 * CDIM + hd * HDIM + d) =
            __floats2half2_rn(oacc[nt][0] * inv0, oacc[nt][1] * inv0);
        *(__half2*)(o + (size_t)(r0 + 8) * CDIM + hd * HDIM + d) =
            __floats2half2_rn(oacc[nt][2] * inv1, oacc[nt][3] * inv1);
    }
}

// ---------------------------------------------------------------------------
// Launcher
// ---------------------------------------------------------------------------
extern "C" void kernel_launch(void* const* d_in, const int* in_sizes, int n_in,
                              void* d_out, int out_size)
{
    const float* x     = (const float*)d_in[0];
    const float* g1    = (const float*)d_in[1];
    const float* g2    = (const float*)d_in[2];
    const float* w_qkv = (const float*)d_in[3];
    const float* w_o   = (const float*)d_in[4];
    const float* w1    = (const float*)d_in[5];
    const float* w2    = (const float*)d_in[6];
    float* out = (float*)d_out;

    __half *h, *qkv, *o, *h2, *t;
    __half *wqkv_h, *wo_h, *w1_h, *w2_h;
    float *x1;
    cudaGetSymbolAddress((void**)&h,   g_h);
    cudaGetSymbolAddress((void**)&qkv, g_qkv);
    cudaGetSymbolAddress((void**)&o,   g_o);
    cudaGetSymbolAddress((void**)&x1,  g_x1);
    cudaGetSymbolAddress((void**)&h2,  g_h2);
    cudaGetSymbolAddress((void**)&t,   g_t);
    cudaGetSymbolAddress((void**)&wqkv_h, g_wqkv_h);
    cudaGetSymbolAddress((void**)&wo_h,   g_wo_h);
    cudaGetSymbolAddress((void**)&w1_h,   g_w1_h);
    cudaGetSymbolAddress((void**)&w2_h,   g_w2_h);

    cudaFuncSetAttribute(hgemm_kernel<1>,
        cudaFuncAttributeMaxDynamicSharedMemorySize, G_SMEM);
    cudaFuncSetAttribute(hgemm_kernel<2>,
        cudaFuncAttributeMaxDynamicSharedMemorySize, G_SMEM);
    cudaFuncSetAttribute(hgemm_kernel<3>,
        cudaFuncAttributeMaxDynamicSharedMemorySize, G_SMEM);

    // 0) all weights -> fp16 in one launch
    f2h_all_kernel<<<(N4_TOTAL + 255) / 256, 256>>>(
        w_qkv, w_o, w1, w2, wqkv_h, wo_h, w1_h, w2_h);

    // 1) h = rmsnorm(x, g1)
    rmsnorm_kernel<<<NTOK, 256>>>(x, g1, h);

    // 2) qkv = h @ w_qkv (q scaled by QSCALE = 0.125*log2e)
    hgemm_kernel<3><<<dim3(QKVDIM / 128, NTOK / 128), 256, G_SMEM>>>(
        h, wqkv_h, nullptr, qkv, NTOK, QKVDIM, CDIM);

    // 3) o = attention(qkv)
    flash_h_kernel<<<dim3(NTOK / 64, NHEAD), 128>>>(qkv, o);

    // 4) x1 = x + o @ w_o
    hgemm_kernel<1><<<dim3(CDIM / 128, NTOK / 128), 256, G_SMEM>>>(
        o, wo_h, x, x1, NTOK, CDIM, CDIM);

    // 5) h2 = rmsnorm(x1, g2)
    rmsnorm_kernel<<<NTOK, 256>>>(x1, g2, h2);

    // 6) t = gelu(h2 @ w1)
    hgemm_kernel<2><<<dim3(MDIM / 128, NTOK / 128), 256, G_SMEM>>>(
        h2, w1_h, nullptr, t, NTOK, MDIM, CDIM);

    // 7) out = x1 + t @ w2
    hgemm_kernel<1><<<dim3(CDIM / 128, NTOK / 128), 256, G_SMEM>>>(
        t, w2_h, x1, out, NTOK, CDIM, MDIM);
}